// round 6
// baseline (speedup 1.0000x reference)
#include <cuda_runtime.h>
#include <math.h>
#include <stdint.h>

// ---------------------------------------------------------------------------
// LSTM + differentiable stack, 259 sequential steps, persistent kernel.
// 128 CTAs x 512 threads, 3 grid barriers per step.
//  Phase A: CTA n -> 16 gate cols (4 units x 4 gates), all 128 batches.
//           W resident in SMEM (dup f32x2). A streamed [k][b] in 64-k chunks
//           via cp.async.bulk double buffer. Thread tile: 2 cols x 8 batches,
//           split-k x4 within each chunk (8 indep FFMA2 chains, 3 LDS : 8 FMA2).
//           Epilogue: split-k reduce in smem, LSTM cell (c in SMEM).
//  Phase R: 49 CTAs: o194 = h @ Wr^T + br (Wr slice in SMEM, 4-way k split).
//  Phase S: CTA b: stack update + log-softmax out (t >= 129).
// ---------------------------------------------------------------------------

#define BATCH   128
#define HID     512
#define INPD    128
#define STKD    64
#define MAXT    259
#define NSTEPS  259
#define KSTART  129
#define OCOLS   194

#define GRIDN   128
#define NTHR    512
#define KCH     64                       // k rows per chunk
#define CHB     (KCH * BATCH * 4)        // 32768 bytes per chunk

// smem layout (float offsets)
#define OFF_WD  0                        // 11264 u64 (W dup f32x2) = 22528 f
#define OFF_AS  22528                    // 2 x (64 x 128) A chunk buffers = 16384 f
#define OFF_GS  38912                    // 16 x 132 gate exchange
#define OFF_SC  41024                    // 512 c-state
#define OFF_SB  41536                    // 16 bias
#define OFF_MB  41552                    // 2 mbarriers
#define SMEMF   41560
#define SMEMB   (SMEMF * 4)

__device__ float d_xT[129 * 128 * 128];      // x transposed [t][k][b]
__device__ float d_RH[(64 + 1024) * 128];    // rows: 0..63 r ; 64..575 h0 ; 576..1087 h1
__device__ float d_h[BATCH * HID];           // batch-major h (for readout)
__device__ float d_s[BATCH * MAXT];
__device__ float d_V[BATCH * MAXT * STKD];
__device__ float d_o194[BATCH * OCOLS];
__device__ unsigned g_bar;

__device__ __forceinline__ float sigf(float x) { return 1.0f / (1.0f + expf(-x)); }

#define FFMA2(acc, a, w) \
    asm volatile("fma.rn.f32x2 %0, %1, %2, %0;" : "+l"(acc) : "l"(a), "l"(w))
#define ADDF2(acc, a) \
    asm volatile("add.rn.f32x2 %0, %0, %1;" : "+l"(acc) : "l"(a))

__device__ __forceinline__ void grid_sync(unsigned &n) {
    __syncthreads();
    n += (unsigned)GRIDN;
    if (threadIdx.x == 0) {
        __threadfence();
        atomicAdd(&g_bar, 1u);
        while (*((volatile unsigned *)&g_bar) < n) { __nanosleep(32); }
        __threadfence();
    }
    __syncthreads();
}

__device__ __forceinline__ void mbar_init(uint32_t mbar) {
    asm volatile("mbarrier.init.shared.b64 [%0], %1;" :: "r"(mbar), "r"(1u) : "memory");
}
__device__ __forceinline__ void mbar_expect(uint32_t mbar, uint32_t bytes) {
    asm volatile("mbarrier.arrive.expect_tx.shared.b64 _, [%0], %1;"
                 :: "r"(mbar), "r"(bytes) : "memory");
}
__device__ __forceinline__ void bulk_ld(uint32_t dst, const float *src,
                                        uint32_t bytes, uint32_t mbar) {
    asm volatile("cp.async.bulk.shared::cluster.global.mbarrier::complete_tx::bytes "
                 "[%0], [%1], %2, [%3];"
                 :: "r"(dst), "l"(src), "r"(bytes), "r"(mbar) : "memory");
}
__device__ __forceinline__ void mbar_wait(uint32_t mbar, uint32_t parity) {
    asm volatile(
        "{\n\t.reg .pred P;\n\t"
        "WL_%=:\n\t"
        "mbarrier.try_wait.parity.acquire.cta.shared::cta.b64 P, [%0], %1, 0x989680;\n\t"
        "@P bra.uni WD_%=;\n\t"
        "bra.uni WL_%=;\n\t"
        "WD_%=:\n\t}"
        :: "r"(mbar), "r"(parity) : "memory");
}

__device__ __forceinline__ const float *chunk_src(int ca, int t, int hrd) {
    if (ca < 2)  return d_xT + ((size_t)t * 128 + ca * 64) * 128;
    if (ca == 2) return d_RH;                                     // r rows
    return d_RH + (size_t)(64 + hrd * 512 + (ca - 3) * 64) * 128; // h rows
}

__global__ void __launch_bounds__(NTHR, 1)
lstm_stack_kernel(const float *__restrict__ x,
                  const float *__restrict__ Wih, const float *__restrict__ bih,
                  const float *__restrict__ Whh, const float *__restrict__ bhh,
                  const float *__restrict__ Wr, const float *__restrict__ br,
                  float *__restrict__ out) {
    extern __shared__ __align__(16) float smf[];
    unsigned long long *Wd = (unsigned long long *)(smf + OFF_WD);
    float *As = smf + OFF_AS;
    float *gs = smf + OFF_GS;
    float *sc = smf + OFF_SC;
    float *sb = smf + OFF_SB;
    // phase aliases of the A-buffer region (TMA idle there)
    unsigned long long *redu = (unsigned long long *)(smf + OFF_AS);
    float *so   = smf + OFF_AS;        // 208
    float *ss   = smf + OFF_AS + 208;  // 288
    float *ssuf = smf + OFF_AS + 496;  // 288
    float *sA   = smf + OFF_AS + 784;  // 288
    float *csum = smf + OFF_AS + 1072; // 32
    float *sred = smf + OFF_AS + 1104; // 512
    float *Wsr  = smf + OFF_AS + 2048; // 2048 (phase R)

    const int tid  = threadIdx.x;
    const int bidx = blockIdx.x;
    const int lane = tid & 31, wid = tid >> 5;
    unsigned n = 0;

    const uint32_t mb0 = (uint32_t)__cvta_generic_to_shared(smf + OFF_MB);
    const uint32_t mb1 = mb0 + 8;
    const uint32_t asb0 = (uint32_t)__cvta_generic_to_shared(As);
    const uint32_t asb1 = asb0 + CHB;
    if (tid == 0) { mbar_init(mb0); mbar_init(mb1); }
    __syncthreads();
    unsigned ph = 0;

    // ---------------- prologue: transpose x[t] -> d_xT[t][k][b] -------------
    {
        float *tile = smf;  // 128x132 scratch (overlaps Wd; W loaded later)
        for (int p = bidx; p < KSTART; p += GRIDN) {
#pragma unroll
            for (int q = 0; q < 8; ++q) {
                int idx = q * 2048 + tid * 4;
                int b = idx >> 7, k = idx & 127;
                float4 v = *(const float4 *)(x + ((size_t)p * 128 + b) * 128 + k);
                tile[b * 132 + k]     = v.x;
                tile[b * 132 + k + 1] = v.y;
                tile[b * 132 + k + 2] = v.z;
                tile[b * 132 + k + 3] = v.w;
            }
            __syncthreads();
#pragma unroll
            for (int q = 0; q < 8; ++q) {
                int idx = q * 2048 + tid * 4;
                int k = idx >> 7, b = idx & 127;
                float4 v = make_float4(tile[b * 132 + k], tile[(b + 1) * 132 + k],
                                       tile[(b + 2) * 132 + k], tile[(b + 3) * 132 + k]);
                *(float4 *)(d_xT + ((size_t)p * 128 + k) * 128 + b) = v;
            }
            __syncthreads();
        }
    }
    grid_sync(n);

    // ---------------- persistent: W dup f32x2, bias, c-state ----------------
    for (int idx = tid; idx < 704 * 16; idx += NTHR) {
        int k = idx >> 4, cidx = idx & 15;
        int m = cidx >> 2, u = cidx & 3;
        int grow = m * 512 + bidx * 4 + u;
        float w = (k < 192) ? Wih[(size_t)grow * 192 + k]
                            : Whh[(size_t)grow * 512 + (k - 192)];
        unsigned ub = __float_as_uint(w);
        Wd[idx] = (unsigned long long)ub | ((unsigned long long)ub << 32);
    }
    if (tid < 16) {
        int m = tid >> 2, u = tid & 3;
        int grow = m * 512 + bidx * 4 + u;
        sb[tid] = bih[grow] + bhh[grow];
    }
    for (int idx = tid; idx < 512; idx += NTHR) sc[idx] = 0.0f;
    __syncthreads();

    const int kq  = tid >> 7;        // k quarter within chunk (0..3)
    const int pos = tid & 127;
    const int cg  = pos & 7;         // col pair (cols cg*2, cg*2+1)
    const int bg  = pos >> 3;        // batch octet (0..15)

    // =========================== main time loop =============================
    for (int t = 0; t < NSTEPS; ++t) {
        const int hrd = t & 1, hwr = (t + 1) & 1;
        const int cbase = (t < KSTART) ? 0 : 2;
        const int nch   = 11 - cbase;

        // ---------------- Phase A: gate GEMM + cell ----------------
        unsigned long long acc[8];
#pragma unroll
        for (int i = 0; i < 8; ++i) acc[i] = 0ull;

        if (tid == 0) {
            mbar_expect(mb0, CHB);
            bulk_ld(asb0, chunk_src(cbase, t, hrd), CHB, mb0);
        }
        for (int ci = 0; ci < nch; ++ci) {
            const int cb = ci & 1;
            if (ci + 1 < nch && tid == 0) {
                const uint32_t mbn = cb ? mb0 : mb1;
                mbar_expect(mbn, CHB);
                bulk_ld(cb ? asb0 : asb1, chunk_src(cbase + ci + 1, t, hrd), CHB, mbn);
            }
            mbar_wait(cb ? mb1 : mb0, (ph >> cb) & 1u);
            ph ^= (1u << cb);

            const float *ka = As + cb * (KCH * BATCH) + kq * 16 * 128 + bg * 8;
            const unsigned long long *kw =
                Wd + ((size_t)(cbase + ci) * 64 + kq * 16) * 16 + cg * 2;
#pragma unroll
            for (int kk = 0; kk < 16; ++kk) {
                ulonglong2 a01 = *(const ulonglong2 *)(ka + kk * 128);
                ulonglong2 a23 = *(const ulonglong2 *)(ka + kk * 128 + 4);
                ulonglong2 w01 = *(const ulonglong2 *)(kw + kk * 16);
                FFMA2(acc[0], a01.x, w01.x);
                FFMA2(acc[1], a01.y, w01.x);
                FFMA2(acc[2], a23.x, w01.x);
                FFMA2(acc[3], a23.y, w01.x);
                FFMA2(acc[4], a01.x, w01.y);
                FFMA2(acc[5], a01.y, w01.y);
                FFMA2(acc[6], a23.x, w01.y);
                FFMA2(acc[7], a23.y, w01.y);
            }
            __syncthreads();
        }
        // ---- split-k reduce ----
        if (kq != 0) {
            unsigned long long *dst = redu + ((size_t)(kq - 1) * 128 + pos) * 8;
#pragma unroll
            for (int i = 0; i < 8; ++i) dst[i] = acc[i];
        }
        __syncthreads();
        if (kq == 0) {
#pragma unroll
            for (int s = 0; s < 3; ++s) {
                const unsigned long long *srcp = redu + ((size_t)s * 128 + pos) * 8;
#pragma unroll
                for (int i = 0; i < 8; ++i) ADDF2(acc[i], srcp[i]);
            }
            // unpack + bias -> gs[col][b]
#pragma unroll
            for (int c = 0; c < 2; ++c) {
                float bsum = sb[cg * 2 + c];
                float v0 = __uint_as_float((unsigned)acc[c * 4 + 0]) + bsum;
                float v1 = __uint_as_float((unsigned)(acc[c * 4 + 0] >> 32)) + bsum;
                float v2 = __uint_as_float((unsigned)acc[c * 4 + 1]) + bsum;
                float v3 = __uint_as_float((unsigned)(acc[c * 4 + 1] >> 32)) + bsum;
                float v4 = __uint_as_float((unsigned)acc[c * 4 + 2]) + bsum;
                float v5 = __uint_as_float((unsigned)(acc[c * 4 + 2] >> 32)) + bsum;
                float v6 = __uint_as_float((unsigned)acc[c * 4 + 3]) + bsum;
                float v7 = __uint_as_float((unsigned)(acc[c * 4 + 3] >> 32)) + bsum;
                float *gp = gs + (cg * 2 + c) * 132 + bg * 8;
                *(float4 *)gp       = make_float4(v0, v1, v2, v3);
                *(float4 *)(gp + 4) = make_float4(v4, v5, v6, v7);
            }
        }
        __syncthreads();
        // cell update: this CTA's 4 hidden units, all 128 batches
        {
            int u = tid >> 7, b = tid & 127;
            float gi = gs[u * 132 + b];
            float gf = gs[(4 + u) * 132 + b];
            float gg = gs[(8 + u) * 132 + b];
            float go = gs[(12 + u) * 132 + b];
            float ig = sigf(gi), fg = sigf(gf);
            float tg = tanhf(gg), og = sigf(go);
            float c2 = fg * sc[tid] + ig * tg;
            sc[tid] = c2;
            float h2 = og * tanhf(c2);
            d_RH[(size_t)(64 + hwr * 512 + bidx * 4 + u) * 128 + b] = h2;
            d_h[(size_t)b * HID + bidx * 4 + u] = h2;
        }
        grid_sync(n);

        // ---------------- Phase R: readout (49 CTAs) ----------------
        if (bidx < 49) {
            const int n0 = bidx * 4;
            for (int idx = tid; idx < 4 * HID; idx += NTHR) {
                int cc = idx >> 9, k = idx & 511, nn = n0 + cc;
                Wsr[idx] = (nn < OCOLS) ? Wr[(size_t)nn * HID + k] : 0.0f;
            }
            __syncthreads();
            const int b  = tid >> 2;
            const int kh = tid & 3;
            const float4 *hv = (const float4 *)(d_h + (size_t)b * HID + kh * 128);
            float acc2[4] = {0.f, 0.f, 0.f, 0.f};
#pragma unroll 8
            for (int k4 = 0; k4 < 32; ++k4) {
                float4 h4 = hv[k4];
                int kk = kh * 128 + k4 * 4;
#pragma unroll
                for (int cc = 0; cc < 4; ++cc) {
                    const float *w = Wsr + cc * HID + kk;
                    acc2[cc] += h4.x * w[0] + h4.y * w[1] + h4.z * w[2] + h4.w * w[3];
                }
            }
#pragma unroll
            for (int cc = 0; cc < 4; ++cc) {
                acc2[cc] += __shfl_down_sync(0xffffffffu, acc2[cc], 2);
                acc2[cc] += __shfl_down_sync(0xffffffffu, acc2[cc], 1);
            }
            if (kh == 0) {
#pragma unroll
                for (int cc = 0; cc < 4; ++cc) {
                    int nn = n0 + cc;
                    if (nn < OCOLS) d_o194[b * OCOLS + nn] = acc2[cc] + br[nn];
                }
            }
        }
        grid_sync(n);

        // ---------------- Phase S: stack update (CTA = batch row) ----------
        const int b = bidx;
        if (tid < OCOLS) so[tid] = d_o194[b * OCOLS + tid];
        for (int i = tid; i < 288; i += NTHR)
            ss[i] = (i < MAXT) ? d_s[b * MAXT + i] : 0.0f;
        __syncthreads();

        if (tid < STKD) d_V[((size_t)b * MAXT + t) * STKD + tid] = so[tid];
        float u_ = sigf(so[192]);
        float dd = sigf(so[193]);

        for (int cch = wid; cch < 9; cch += 16) {
            float v = ss[cch * 32 + lane];
#pragma unroll
            for (int o = 1; o < 32; o <<= 1) {
                float tv = __shfl_down_sync(0xffffffffu, v, o);
                if (lane + o < 32) v += tv;
            }
            ssuf[cch * 32 + lane] = v;
            if (lane == 0) csum[cch] = v;
        }
        __syncthreads();
        if (wid == 0) {
            float tv = (lane < 9) ? csum[lane] : 0.0f;
            float vv = tv;
#pragma unroll
            for (int o = 1; o < 16; o <<= 1) {
                float sh = __shfl_down_sync(0xffffffffu, vv, o);
                if (lane + o < 16) vv += sh;
            }
            if (lane < 9) csum[lane] = vv - tv;
        }
        __syncthreads();

        for (int i = tid; i < MAXT; i += NTHR) {
            float si   = ss[i];
            float prod = ssuf[i] + csum[i >> 5] - si;
            float sp   = fmaxf(0.0f, si - fmaxf(0.0f, u_ - prod));
            if (i == t) sp = dd;
            float inner = fmaxf(0.0f, 1.0f - prod - sp);
            sA[i] = fminf(sp, inner);
            if (i <= t) d_s[b * MAXT + i] = sp;
        }
        __syncthreads();

        {
            const int dcol = tid & 63, q = tid >> 6;   // q 0..7
            float acc3 = 0.0f;
            for (int i = q; i <= t; i += 8)
                acc3 += sA[i] * d_V[((size_t)b * MAXT + i) * STKD + dcol];
            sred[q * 64 + dcol] = acc3;
        }
        __syncthreads();
        if (tid < STKD) {
            float r = 0.0f;
#pragma unroll
            for (int q = 0; q < 8; ++q) r += sred[q * 64 + tid];
            d_RH[(size_t)tid * 128 + b] = r;
        }

        if (t >= KSTART) {
            __syncthreads();
            float v = (tid < INPD) ? so[STKD + tid] : -1e30f;
            float m = v;
#pragma unroll
            for (int o = 16; o; o >>= 1) m = fmaxf(m, __shfl_xor_sync(0xffffffffu, m, o));
            if (lane == 0) csum[wid] = m;
            __syncthreads();
            float mm = csum[0];
#pragma unroll
            for (int w = 1; w < 16; ++w) mm = fmaxf(mm, csum[w]);
            float e = (tid < INPD) ? expf(v - mm) : 0.0f;
#pragma unroll
            for (int o = 16; o; o >>= 1) e += __shfl_xor_sync(0xffffffffu, e, o);
            if (lane == 0) csum[16 + wid] = e;
            __syncthreads();
            float tot = 0.0f;
#pragma unroll
            for (int w = 0; w < 16; ++w) tot += csum[16 + w];
            float ls = logf(tot);
            if (tid < INPD)
                out[(((size_t)(t - KSTART)) * BATCH + b) * INPD + tid] = v - mm - ls;
        }
        grid_sync(n);
    }
}

extern "C" void kernel_launch(void *const *d_in, const int *in_sizes, int n_in,
                              void *d_out, int out_size) {
    (void)in_sizes; (void)n_in; (void)out_size;
    const float *x   = (const float *)d_in[0];
    const float *Wih = (const float *)d_in[1];
    const float *bih = (const float *)d_in[2];
    const float *Whh = (const float *)d_in[3];
    const float *bhh = (const float *)d_in[4];
    const float *Wr  = (const float *)d_in[5];
    const float *br  = (const float *)d_in[6];
    float *out = (float *)d_out;

    cudaFuncSetAttribute(lstm_stack_kernel,
                         cudaFuncAttributeMaxDynamicSharedMemorySize, SMEMB);

    void *p;
    cudaGetSymbolAddress(&p, d_RH);  cudaMemsetAsync(p, 0, sizeof(float) * (64 + 1024) * 128);
    cudaGetSymbolAddress(&p, d_s);   cudaMemsetAsync(p, 0, sizeof(float) * BATCH * MAXT);
    cudaGetSymbolAddress(&p, g_bar); cudaMemsetAsync(p, 0, sizeof(unsigned));

    lstm_stack_kernel<<<GRIDN, NTHR, SMEMB>>>(x, Wih, bih, Whh, bhh, Wr, br, out);
}

// round 7
// speedup vs baseline: 2.0714x; 2.0714x over previous
#include <cuda_runtime.h>
#include <math.h>
#include <stdint.h>

// ---------------------------------------------------------------------------
// LSTM + differentiable stack, 259 steps, persistent kernel, 128 CTAs x 256 thr.
// Per step, 3 grid barriers:
//  I1: gates_{t+1} partial over h_t (8 chunks) [+ x_{t+1} (2 chunks) if t<128]
//      + fused readout o194_t (2 cols/CTA, Wr persistent in smem).
//  I2: CTA b: stack update (V,s persistent in smem!) -> r_t ; log-softmax out.
//  I3: gates r-chunk (1) + bias + LSTM cell -> h_{t+1} (transposed).
// Weights scalar in smem, duplicated to f32x2 via mov.b64 at use.
// ---------------------------------------------------------------------------

#define BATCH   128
#define HID     512
#define INPD    128
#define STKD    64
#define MAXT    259
#define NSTEPS  259
#define KSTART  129
#define OCOLS   194

#define GRIDN   128
#define NTHR    256
#define KCH     64
#define CHB     (KCH * BATCH * 4)        // 32768 B per chunk

// smem float offsets
#define OFF_WS   0                       // 704 x 16 scalar W
#define OFF_AS   11264                   // 2 x (64 x 128) A chunk buffers
#define OFF_V    27648                   // 259 x 64 stack V (persistent)
#define OFF_WRS  44224                   // 2 x 512 Wr cols (persistent)
#define OFF_GS   45248                   // 16 x 132 gate exchange
#define OFF_SC   47360                   // 512 c-state (persistent)
#define OFF_SB   47872                   // 16 gate bias
#define OFF_SBR  47888                   // 2 readout bias
#define OFF_SS   47890                   // 292 stack s (persistent)
#define OFF_MB   48184                   // 2 mbarriers
#define OFF_SO   48192                   // 208 o194 row
#define OFF_SUF  48400                   // 288 suffix
#define OFF_SA   48688                   // 288 A coeffs
#define OFF_CS   48976                   // 32
#define OFF_SRD  49008                   // 256 gather reduce
#define OFF_SRR  49264                   // 1024 readout reduce
#define SMEMF    50288
#define SMEMB    (SMEMF * 4)

__device__ float d_xT[129 * 128 * 128];      // x transposed [t][k][b]
__device__ float d_RH[(64 + 512) * 128];     // rows 0..63: r ; 64..575: h  ([k][b])
__device__ float d_o194T[OCOLS * 128];       // readout transposed [n][b]
__device__ unsigned g_bar;

__device__ __forceinline__ float sigf(float x) { return 1.0f / (1.0f + expf(-x)); }

#define FFMA2(acc, a, w) \
    asm volatile("fma.rn.f32x2 %0, %1, %2, %0;" : "+l"(acc) : "l"(a), "l"(w))
#define DUP2(d, s) \
    asm volatile("mov.b64 %0, {%1, %1};" : "=l"(d) : "r"(__float_as_uint(s)))

__device__ __forceinline__ void grid_sync(unsigned &n) {
    __syncthreads();
    n += (unsigned)GRIDN;
    if (threadIdx.x == 0) {
        __threadfence();
        atomicAdd(&g_bar, 1u);
        while (*((volatile unsigned *)&g_bar) < n) { __nanosleep(16); }
        __threadfence();
    }
    __syncthreads();
}

__device__ __forceinline__ void mbar_init(uint32_t mbar) {
    asm volatile("mbarrier.init.shared.b64 [%0], %1;" :: "r"(mbar), "r"(1u) : "memory");
}
__device__ __forceinline__ void mbar_expect(uint32_t mbar, uint32_t bytes) {
    asm volatile("mbarrier.arrive.expect_tx.shared.b64 _, [%0], %1;"
                 :: "r"(mbar), "r"(bytes) : "memory");
}
__device__ __forceinline__ void bulk_ld(uint32_t dst, const float *src,
                                        uint32_t bytes, uint32_t mbar) {
    asm volatile("cp.async.bulk.shared::cluster.global.mbarrier::complete_tx::bytes "
                 "[%0], [%1], %2, [%3];"
                 :: "r"(dst), "l"(src), "r"(bytes), "r"(mbar) : "memory");
}
__device__ __forceinline__ void mbar_wait(uint32_t mbar, uint32_t parity) {
    asm volatile(
        "{\n\t.reg .pred P;\n\t"
        "WL_%=:\n\t"
        "mbarrier.try_wait.parity.acquire.cta.shared::cta.b64 P, [%0], %1, 0x989680;\n\t"
        "@P bra.uni WD_%=;\n\t"
        "bra.uni WL_%=;\n\t"
        "WD_%=:\n\t}"
        :: "r"(mbar), "r"(parity) : "memory");
}

struct Pipe {
    uint32_t mb0, mb1, as0, as1;
    unsigned ph;
    __device__ __forceinline__ void prefetch(int buf, const float *src, bool issuer) {
        if (issuer) {
            uint32_t mb = buf ? mb1 : mb0;
            mbar_expect(mb, CHB);
            bulk_ld(buf ? as1 : as0, src, CHB, mb);
        }
    }
    __device__ __forceinline__ void wait(int buf) {
        mbar_wait(buf ? mb1 : mb0, (ph >> buf) & 1u);
        ph ^= (1u << buf);
    }
};

__global__ void __launch_bounds__(NTHR, 1)
lstm_stack_kernel(const float *__restrict__ x,
                  const float *__restrict__ Wih, const float *__restrict__ bih,
                  const float *__restrict__ Whh, const float *__restrict__ bhh,
                  const float *__restrict__ Wr, const float *__restrict__ br,
                  float *__restrict__ out) {
    extern __shared__ __align__(16) float smf[];
    float *Ws   = smf + OFF_WS;
    float *As   = smf + OFF_AS;
    float *Vs   = smf + OFF_V;
    float *Wrs  = smf + OFF_WRS;
    float *gs   = smf + OFF_GS;
    float *sc   = smf + OFF_SC;
    float *sb   = smf + OFF_SB;
    float *sbr  = smf + OFF_SBR;
    float *ss   = smf + OFF_SS;
    float *so   = smf + OFF_SO;
    float *ssuf = smf + OFF_SUF;
    float *sA   = smf + OFF_SA;
    float *csum = smf + OFF_CS;
    float *sred = smf + OFF_SRD;
    float *srr  = smf + OFF_SRR;

    const int tid  = threadIdx.x;
    const int bidx = blockIdx.x;
    const int lane = tid & 31, wid = tid >> 5;
    unsigned n = 0;

    Pipe pipe;
    pipe.mb0 = (uint32_t)__cvta_generic_to_shared(smf + OFF_MB);
    pipe.mb1 = pipe.mb0 + 8;
    pipe.as0 = (uint32_t)__cvta_generic_to_shared(As);
    pipe.as1 = pipe.as0 + CHB;
    pipe.ph  = 0;
    if (tid == 0) { mbar_init(pipe.mb0); mbar_init(pipe.mb1); }
    __syncthreads();

    // ---------------- prologue: transpose x[t] -> d_xT[t][k][b] -------------
    {
        float *tile = smf;  // 128x132 scratch inside Ws+As region (loaded later)
        for (int p = bidx; p < KSTART; p += GRIDN) {
#pragma unroll
            for (int q = 0; q < 16; ++q) {
                int idx = q * 1024 + tid * 4;
                int b = idx >> 7, k = idx & 127;
                float4 v = *(const float4 *)(x + ((size_t)p * 128 + b) * 128 + k);
                tile[b * 132 + k]     = v.x;
                tile[b * 132 + k + 1] = v.y;
                tile[b * 132 + k + 2] = v.z;
                tile[b * 132 + k + 3] = v.w;
            }
            __syncthreads();
#pragma unroll
            for (int q = 0; q < 16; ++q) {
                int idx = q * 1024 + tid * 4;
                int k = idx >> 7, b = idx & 127;
                float4 v = make_float4(tile[b * 132 + k], tile[(b + 1) * 132 + k],
                                       tile[(b + 2) * 132 + k], tile[(b + 3) * 132 + k]);
                *(float4 *)(d_xT + ((size_t)p * 128 + k) * 128 + b) = v;
            }
            __syncthreads();
        }
    }
    grid_sync(n);

    // ---------------- persistent loads ----------------
    for (int idx = tid; idx < 704 * 16; idx += NTHR) {
        int k = idx >> 4, cidx = idx & 15;
        int m = cidx >> 2, u = cidx & 3;
        int grow = m * 512 + bidx * 4 + u;
        Ws[idx] = (k < 192) ? Wih[(size_t)grow * 192 + k]
                            : Whh[(size_t)grow * 512 + (k - 192)];
    }
    for (int idx = tid; idx < 1024; idx += NTHR) {
        int c = idx >> 9, k = idx & 511;
        int nn = bidx + c * 128;
        Wrs[idx] = (nn < OCOLS) ? Wr[(size_t)nn * HID + k] : 0.0f;
    }
    if (tid < 16) {
        int m = tid >> 2, u = tid & 3;
        int grow = m * 512 + bidx * 4 + u;
        sb[tid] = bih[grow] + bhh[grow];
    }
    if (tid < 2) {
        int nn = bidx + tid * 128;
        sbr[tid] = (nn < OCOLS) ? br[nn] : 0.0f;
    }
    for (int idx = tid; idx < 512; idx += NTHR) sc[idx] = 0.0f;
    for (int idx = tid; idx < 292; idx += NTHR) ss[idx] = 0.0f;
    for (int idx = tid; idx < MAXT * STKD; idx += NTHR) Vs[idx] = 0.0f;
    __syncthreads();

    // GEMM thread mapping: 2 cols x 4 batches
    const int tx = tid & 7;      // col-pair (cols 2tx, 2tx+1)
    const int bq = tid >> 3;     // batch quad (0..31)
    // readout mapping
    const int rc  = tid >> 7;            // col 0/1
    const int rks = (tid >> 5) & 3;      // k-split
    const int rbq = tid & 31;            // batch quad

    unsigned long long acc00, acc01, acc10, acc11;

    // ================= init interval: gates_0 = x_0 part; cell -> h_0 =======
    acc00 = acc01 = acc10 = acc11 = 0ull;
    pipe.prefetch(0, d_xT, tid == 0);
#pragma unroll 1
    for (int ci = 0; ci < 2; ++ci) {
        if (ci == 0) pipe.prefetch(1, d_xT + 64 * 128, tid == 0);
        pipe.wait(ci & 1);
        const float *Ab = As + (ci & 1) * (KCH * BATCH);
        const float *wp = Ws + (size_t)(ci * 64) * 16 + tx * 2;
#pragma unroll 16
        for (int kk = 0; kk < KCH; ++kk) {
            ulonglong2 a = *(const ulonglong2 *)(Ab + kk * 128 + bq * 4);
            float2 w = *(const float2 *)(wp + kk * 16);
            unsigned long long w0, w1;
            DUP2(w0, w.x); DUP2(w1, w.y);
            FFMA2(acc00, a.x, w0); FFMA2(acc01, a.y, w0);
            FFMA2(acc10, a.x, w1); FFMA2(acc11, a.y, w1);
        }
        __syncthreads();
    }
    // epilogue -> gs -> cell
    {
        float b0 = sb[tx * 2], b1 = sb[tx * 2 + 1];
        float *g0 = gs + (tx * 2) * 132 + bq * 4;
        float *g1 = gs + (tx * 2 + 1) * 132 + bq * 4;
        *(float4 *)g0 = make_float4(__uint_as_float((unsigned)acc00) + b0,
                                    __uint_as_float((unsigned)(acc00 >> 32)) + b0,
                                    __uint_as_float((unsigned)acc01) + b0,
                                    __uint_as_float((unsigned)(acc01 >> 32)) + b0);
        *(float4 *)g1 = make_float4(__uint_as_float((unsigned)acc10) + b1,
                                    __uint_as_float((unsigned)(acc10 >> 32)) + b1,
                                    __uint_as_float((unsigned)acc11) + b1,
                                    __uint_as_float((unsigned)(acc11 >> 32)) + b1);
    }
    __syncthreads();
#pragma unroll
    for (int r = 0; r < 2; ++r) {
        int idx = tid + r * NTHR;
        int u = idx >> 7, b = idx & 127;
        float gi = gs[u * 132 + b];
        float gf = gs[(4 + u) * 132 + b];
        float gg = gs[(8 + u) * 132 + b];
        float go = gs[(12 + u) * 132 + b];
        float c2 = sigf(gf) * sc[idx] + sigf(gi) * tanhf(gg);
        sc[idx] = c2;
        d_RH[(size_t)(64 + bidx * 4 + u) * 128 + b] = sigf(go) * tanhf(c2);
    }
    grid_sync(n);

    // =========================== main time loop =============================
    for (int t = 0; t < NSTEPS; ++t) {
        const int xoff = (t < 128) ? 2 : 0;
        const int nch  = 8 + xoff;

        // ---------- I1: h/x gate chunks + fused readout ----------
        acc00 = acc01 = acc10 = acc11 = 0ull;
        float4 racc = make_float4(0.f, 0.f, 0.f, 0.f);

        const float *src0 = xoff ? (d_xT + ((size_t)(t + 1) * 128) * 128)
                                 : (d_RH + (size_t)64 * 128);
        pipe.prefetch(0, src0, tid == 0);
#pragma unroll 1
        for (int ci = 0; ci < nch; ++ci) {
            if (ci + 1 < nch) {
                const float *srcn = (ci + 1 < xoff)
                    ? (d_xT + ((size_t)(t + 1) * 128 + (ci + 1) * 64) * 128)
                    : (d_RH + (size_t)(64 + (ci + 1 - xoff) * 64) * 128);
                pipe.prefetch((ci + 1) & 1, srcn, tid == 0);
            }
            pipe.wait(ci & 1);
            const float *Ab = As + (ci & 1) * (KCH * BATCH);
            const int wrow = (ci < xoff) ? ci * 64 : 192 + (ci - xoff) * 64;
            const float *wp = Ws + (size_t)wrow * 16 + tx * 2;
#pragma unroll 16
            for (int kk = 0; kk < KCH; ++kk) {
                ulonglong2 a = *(const ulonglong2 *)(Ab + kk * 128 + bq * 4);
                float2 w = *(const float2 *)(wp + kk * 16);
                unsigned long long w0, w1;
                DUP2(w0, w.x); DUP2(w1, w.y);
                FFMA2(acc00, a.x, w0); FFMA2(acc01, a.y, w0);
                FFMA2(acc10, a.x, w1); FFMA2(acc11, a.y, w1);
            }
            if (ci >= xoff) {  // readout over h chunks
                const int j = ci - xoff;
                const float *Ar = Ab + (rks * 16) * 128 + rbq * 4;
                const float *wr = Wrs + rc * 512 + j * 64 + rks * 16;
#pragma unroll 16
                for (int m = 0; m < 16; ++m) {
                    float4 a4 = *(const float4 *)(Ar + m * 128);
                    float w = wr[m];
                    racc.x = fmaf(a4.x, w, racc.x);
                    racc.y = fmaf(a4.y, w, racc.y);
                    racc.z = fmaf(a4.z, w, racc.z);
                    racc.w = fmaf(a4.w, w, racc.w);
                }
            }
            __syncthreads();
        }
        // readout reduce + store o194T
        *(float4 *)(srr + rks * 256 + rc * 128 + rbq * 4) = racc;
        __syncthreads();
        {
            int c = tid >> 7, b = tid & 127;
            int nn = bidx + c * 128;
            if (nn < OCOLS) {
                float o = srr[b + c * 128] + srr[256 + b + c * 128] +
                          srr[512 + b + c * 128] + srr[768 + b + c * 128] + sbr[c];
                d_o194T[(size_t)nn * 128 + b] = o;
            }
        }
        grid_sync(n);

        // ---------- I2: stack update for batch b = bidx ----------
        const int b = bidx;
        if (tid < OCOLS) so[tid] = d_o194T[(size_t)tid * 128 + b];
        __syncthreads();

        if (tid < STKD) Vs[t * STKD + tid] = so[tid];
        float u_ = sigf(so[192]);
        float dd = sigf(so[193]);

        for (int cch = wid; cch < 9; cch += 8) {
            float v = ss[cch * 32 + lane];
#pragma unroll
            for (int o = 1; o < 32; o <<= 1) {
                float tv = __shfl_down_sync(0xffffffffu, v, o);
                if (lane + o < 32) v += tv;
            }
            ssuf[cch * 32 + lane] = v;
            if (lane == 0) csum[cch] = v;
        }
        __syncthreads();
        if (wid == 0) {
            float tv = (lane < 9) ? csum[lane] : 0.0f;
            float vv = tv;
#pragma unroll
            for (int o = 1; o < 16; o <<= 1) {
                float sh = __shfl_down_sync(0xffffffffu, vv, o);
                if (lane + o < 16) vv += sh;
            }
            if (lane < 9) csum[lane] = vv - tv;
        }
        __syncthreads();

        for (int i = tid; i < MAXT; i += NTHR) {
            float si   = ss[i];
            float prod = ssuf[i] + csum[i >> 5] - si;
            float sp   = fmaxf(0.0f, si - fmaxf(0.0f, u_ - prod));
            if (i == t) sp = dd;
            float inner = fmaxf(0.0f, 1.0f - prod - sp);
            sA[i] = fminf(sp, inner);
            if (i <= t) ss[i] = sp;
        }
        __syncthreads();

        // r_t[d] = sum_{i<=t} A[i] * V[i][d]   (all smem, 4-way MLP)
        {
            const int dcol = tid & 63, q = tid >> 6;   // q 0..3, stride 4
            float a0 = 0.f, a1 = 0.f, a2 = 0.f, a3 = 0.f;
            int i = q;
            for (; i + 12 <= t; i += 16) {
                a0 = fmaf(sA[i],      Vs[i * 64 + dcol],        a0);
                a1 = fmaf(sA[i + 4],  Vs[(i + 4) * 64 + dcol],  a1);
                a2 = fmaf(sA[i + 8],  Vs[(i + 8) * 64 + dcol],  a2);
                a3 = fmaf(sA[i + 12], Vs[(i + 12) * 64 + dcol], a3);
            }
            for (; i <= t; i += 4)
                a0 = fmaf(sA[i], Vs[i * 64 + dcol], a0);
            sred[q * 64 + dcol] = (a0 + a1) + (a2 + a3);
        }
        __syncthreads();
        if (tid < STKD)
            d_RH[(size_t)tid * 128 + b] =
                sred[tid] + sred[64 + tid] + sred[128 + tid] + sred[192 + tid];

        if (t >= KSTART) {
            float v = (tid < INPD) ? so[STKD + tid] : -1e30f;
            float m = v;
#pragma unroll
            for (int o = 16; o; o >>= 1) m = fmaxf(m, __shfl_xor_sync(0xffffffffu, m, o));
            if (lane == 0) csum[wid] = m;
            __syncthreads();
            float mm = csum[0];
#pragma unroll
            for (int w = 1; w < 8; ++w) mm = fmaxf(mm, csum[w]);
            float e = (tid < INPD) ? expf(v - mm) : 0.0f;
#pragma unroll
            for (int o = 16; o; o >>= 1) e += __shfl_xor_sync(0xffffffffu, e, o);
            if (lane == 0) csum[8 + wid] = e;
            __syncthreads();
            float tot = 0.0f;
#pragma unroll
            for (int w = 0; w < 8; ++w) tot += csum[8 + w];
            float ls = logf(tot);
            if (tid < INPD)
                out[(((size_t)(t - KSTART)) * BATCH + b) * INPD + tid] = v - mm - ls;
        }
        grid_sync(n);

        if (t == NSTEPS - 1) break;

        // ---------- I3: r-chunk + bias + cell -> h_{t+1} ----------
        pipe.prefetch(0, d_RH, tid == 0);
        pipe.wait(0);
        {
            const float *Ab = As;
            const float *wp = Ws + (size_t)128 * 16 + tx * 2;
#pragma unroll 16
            for (int kk = 0; kk < KCH; ++kk) {
                ulonglong2 a = *(const ulonglong2 *)(Ab + kk * 128 + bq * 4);
                float2 w = *(const float2 *)(wp + kk * 16);
                unsigned long long w0, w1;
                DUP2(w0, w.x); DUP2(w1, w.y);
                FFMA2(acc00, a.x, w0); FFMA2(acc01, a.y, w0);
                FFMA2(acc10, a.x, w1); FFMA2(acc11, a.y, w1);
            }
        }
        __syncthreads();
        {
            float b0 = sb[tx * 2], b1 = sb[tx * 2 + 1];
            float *g0 = gs + (tx * 2) * 132 + bq * 4;
            float *g1 = gs + (tx * 2 + 1) * 132 + bq * 4;
            *(float4 *)g0 = make_float4(__uint_as_float((unsigned)acc00) + b0,
                                        __uint_as_float((unsigned)(acc00 >> 32)) + b0,
                                        __uint_as_float((unsigned)acc01) + b0,
                                        __uint_as_float((unsigned)(acc01 >> 32)) + b0);
            *(float4 *)g1 = make_float4(__uint_as_float((unsigned)acc10) + b1,
                                        __uint_as_float((unsigned)(acc10 >> 32)) + b1,
                                        __uint_as_float((unsigned)acc11) + b1,
                                        __uint_as_float((unsigned)(acc11 >> 32)) + b1);
        }
        __syncthreads();
#pragma unroll
        for (int r = 0; r < 2; ++r) {
            int idx = tid + r * NTHR;
            int u = idx >> 7, bb = idx & 127;
            float gi = gs[u * 132 + bb];
            float gf = gs[(4 + u) * 132 + bb];
            float gg = gs[(8 + u) * 132 + bb];
            float go = gs[(12 + u) * 132 + bb];
            float c2 = sigf(gf) * sc[idx] + sigf(gi) * tanhf(gg);
            sc[idx] = c2;
            d_RH[(size_t)(64 + bidx * 4 + u) * 128 + bb] = sigf(go) * tanhf(c2);
        }
        grid_sync(n);
    }
}

extern "C" void kernel_launch(void *const *d_in, const int *in_sizes, int n_in,
                              void *d_out, int out_size) {
    (void)in_sizes; (void)n_in; (void)out_size;
    const float *x   = (const float *)d_in[0];
    const float *Wih = (const float *)d_in[1];
    const float *bih = (const float *)d_in[2];
    const float *Whh = (const float *)d_in[3];
    const float *bhh = (const float *)d_in[4];
    const float *Wr  = (const float *)d_in[5];
    const float *br  = (const float *)d_in[6];
    float *out = (float *)d_out;

    cudaFuncSetAttribute(lstm_stack_kernel,
                         cudaFuncAttributeMaxDynamicSharedMemorySize, SMEMB);

    void *p;
    cudaGetSymbolAddress(&p, d_RH);  cudaMemsetAsync(p, 0, sizeof(float) * (64 + 512) * 128);
    cudaGetSymbolAddress(&p, g_bar); cudaMemsetAsync(p, 0, sizeof(unsigned));

    lstm_stack_kernel<<<GRIDN, NTHR, SMEMB>>>(x, Wih, bih, Whh, bhh, Wr, br, out);
}